// round 2
// baseline (speedup 1.0000x reference)
#include <cuda_runtime.h>
#include <cuda_bf16.h>
#include <cstdint>

// ---------------------------------------------------------------------------
// GAT layer: out = concat( softmax(mask(lrelu(s_i + t_j))) @ h , h )
//   X:[1024,75,512] fp32   A:[75,75] int32   W:[512,256] fp32   a:[2,256,1] fp32
//   out:[1024,75,512] fp32
// Phase 1: h = X @ W  -> written to out[..., 256:512]
// Phase 2: attention + aggregation -> out[..., 0:256]
// ---------------------------------------------------------------------------

#define BATCH 1024
#define NNODE 75
#define FIN   512
#define FOUT  256
#define MROWS (BATCH * NNODE)   // 76800

// ===================== Phase 1: SGEMM (M=76800, K=512, N=256) ==============
// 128x128 block tile, BK=16, 256 threads, 8x8 per-thread register tile,
// register-staged double buffering (prefetch tile k+1 while computing tile k).

#define BM 128
#define BN 128
#define BK 16
#define TM 8
#define TN 8
#define NKTILES (FIN / BK)   // 32

__global__ __launch_bounds__(256, 2)
void gat_gemm_kernel(const float* __restrict__ X,
                     const float* __restrict__ W,
                     float* __restrict__ out)
{
    __shared__ float As[2][BK][BM];   // transposed A tile: [k][m]
    __shared__ float Bs[2][BK][BN];

    const int tid = threadIdx.x;
    const int threadCol = tid % (BN / TN);   // 0..15
    const int threadRow = tid / (BN / TN);   // 0..15

    const float* Ap = X + (size_t)blockIdx.y * BM * FIN;
    const float* Bp = W + blockIdx.x * BN;

    // A-tile loader: 128 rows x 16 k = 2048 floats = 256 thr * 2 float4
    const int aRow  = tid >> 2;        // 0..63 (plus +64)
    const int aCol4 = tid & 3;         // float4 index along K
    // B-tile loader: 16 k-rows x 128 cols = 2048 floats
    const int bRow  = tid >> 5;        // 0..7 (plus +8)
    const int bCol4 = tid & 31;        // float4 index along N

    float acc[TM][TN];
    #pragma unroll
    for (int i = 0; i < TM; i++)
        #pragma unroll
        for (int j = 0; j < TN; j++) acc[i][j] = 0.0f;

    float4 aReg[2], bReg[2];

    // ---- preload tile 0 into buffer 0 ----
    #pragma unroll
    for (int r = 0; r < 2; r++)
        aReg[r] = *reinterpret_cast<const float4*>(
            Ap + (size_t)(aRow + r * 64) * FIN + aCol4 * 4);
    #pragma unroll
    for (int r = 0; r < 2; r++)
        bReg[r] = *reinterpret_cast<const float4*>(
            Bp + (size_t)(bRow + r * 8) * FOUT + bCol4 * 4);

    #pragma unroll
    for (int r = 0; r < 2; r++) {
        As[0][aCol4 * 4 + 0][aRow + r * 64] = aReg[r].x;
        As[0][aCol4 * 4 + 1][aRow + r * 64] = aReg[r].y;
        As[0][aCol4 * 4 + 2][aRow + r * 64] = aReg[r].z;
        As[0][aCol4 * 4 + 3][aRow + r * 64] = aReg[r].w;
        *reinterpret_cast<float4*>(&Bs[0][bRow + r * 8][bCol4 * 4]) = bReg[r];
    }
    __syncthreads();

    int cur = 0;
    #pragma unroll 1
    for (int t = 0; t < NKTILES; t++) {
        // ---- issue global prefetch for tile t+1 (latency hidden by compute) ----
        if (t + 1 < NKTILES) {
            const int k0 = (t + 1) * BK;
            #pragma unroll
            for (int r = 0; r < 2; r++)
                aReg[r] = *reinterpret_cast<const float4*>(
                    Ap + (size_t)(aRow + r * 64) * FIN + k0 + aCol4 * 4);
            #pragma unroll
            for (int r = 0; r < 2; r++)
                bReg[r] = *reinterpret_cast<const float4*>(
                    Bp + (size_t)(k0 + bRow + r * 8) * FOUT + bCol4 * 4);
        }

        // ---- compute on buffer cur ----
        #pragma unroll
        for (int k = 0; k < BK; k++) {
            float4 am0 = *reinterpret_cast<const float4*>(&As[cur][k][threadRow * TM]);
            float4 am1 = *reinterpret_cast<const float4*>(&As[cur][k][threadRow * TM + 4]);
            float4 bn0 = *reinterpret_cast<const float4*>(&Bs[cur][k][threadCol * TN]);
            float4 bn1 = *reinterpret_cast<const float4*>(&Bs[cur][k][threadCol * TN + 4]);
            float regM[TM] = {am0.x, am0.y, am0.z, am0.w, am1.x, am1.y, am1.z, am1.w};
            float regN[TN] = {bn0.x, bn0.y, bn0.z, bn0.w, bn1.x, bn1.y, bn1.z, bn1.w};
            #pragma unroll
            for (int i = 0; i < TM; i++)
                #pragma unroll
                for (int j = 0; j < TN; j++)
                    acc[i][j] = fmaf(regM[i], regN[j], acc[i][j]);
        }

        // ---- commit prefetched tile into the other buffer ----
        if (t + 1 < NKTILES) {
            const int nxt = cur ^ 1;
            #pragma unroll
            for (int r = 0; r < 2; r++) {
                As[nxt][aCol4 * 4 + 0][aRow + r * 64] = aReg[r].x;
                As[nxt][aCol4 * 4 + 1][aRow + r * 64] = aReg[r].y;
                As[nxt][aCol4 * 4 + 2][aRow + r * 64] = aReg[r].z;
                As[nxt][aCol4 * 4 + 3][aRow + r * 64] = aReg[r].w;
                *reinterpret_cast<float4*>(&Bs[nxt][bRow + r * 8][bCol4 * 4]) = bReg[r];
            }
            __syncthreads();
            cur = nxt;
        }
    }

    // Write h to out[..., 256 + n] (row stride = 512).
    float* Cp = out + (size_t)(blockIdx.y * BM) * 512 + 256 + blockIdx.x * BN;
    #pragma unroll
    for (int i = 0; i < TM; i++) {
        const int row = threadRow * TM + i;
        #pragma unroll
        for (int j = 0; j < TN; j += 4) {
            float4 v = make_float4(acc[i][j], acc[i][j + 1], acc[i][j + 2], acc[i][j + 3]);
            *reinterpret_cast<float4*>(Cp + (size_t)row * 512 + threadCol * TN + j) = v;
        }
    }
}

// ===================== Phase 2: attention + aggregation ====================
// One block per batch. 256 threads. Dynamic smem layout (floats):
//   hs [75*256]   h tile
//   mb [5632]     mask bias (0 or -1e9), layout i*75+j
//   sv [80]       s_i  (h . a0)
//   tv [80]       t_j  (h . a1)
//   al [5*80]     5 normalized alpha rows per group
#define SM_HS   0
#define SM_MB   (SM_HS + NNODE * FOUT)          // 19200
#define SM_SV   (SM_MB + 5632)                  // 24832
#define SM_TV   (SM_SV + 80)                    // 24912
#define SM_AL   (SM_TV + 80)                    // 24992
#define SM_TOTF (SM_AL + 5 * 80)                // 25392 floats
#define SMEM_BYTES (SM_TOTF * 4)                // 101568 bytes

__global__ __launch_bounds__(256, 2)
void gat_attn_kernel(const int* __restrict__ A,
                     const float* __restrict__ avec,  // [2*256]
                     float* __restrict__ out)
{
    extern __shared__ float sm[];
    float* hs = sm + SM_HS;
    float* mb = sm + SM_MB;
    float* sv = sm + SM_SV;
    float* tv = sm + SM_TV;
    float* al = sm + SM_AL;

    const int b    = blockIdx.x;
    const int tid  = threadIdx.x;
    const int warp = tid >> 5;
    const int lane = tid & 31;

    float* outb = out + (size_t)b * NNODE * 512;
    const float* hsrc = outb + 256;

    // Load h[b] (stride 512 -> packed 256), float4 per thread step.
    for (int idx = tid; idx < NNODE * (FOUT / 4); idx += 256) {
        const int i = idx / 64;          // node
        const int f4 = idx % 64;         // float4 within row
        *reinterpret_cast<float4*>(&hs[i * FOUT + f4 * 4]) =
            *reinterpret_cast<const float4*>(hsrc + (size_t)i * 512 + f4 * 4);
    }
    // Mask bias
    for (int idx = tid; idx < NNODE * NNODE; idx += 256)
        mb[idx] = A[idx] ? 0.0f : -1.0e9f;
    __syncthreads();

    // s_i = h_i . a0 ; t_i = h_i . a1  (warp per row)
    for (int i = warp; i < NNODE; i += 8) {
        float s0 = 0.0f, s1 = 0.0f;
        #pragma unroll
        for (int r = 0; r < 8; r++) {
            const int f = lane + r * 32;
            const float hv = hs[i * FOUT + f];
            s0 = fmaf(hv, avec[f], s0);
            s1 = fmaf(hv, avec[256 + f], s1);
        }
        #pragma unroll
        for (int o = 16; o; o >>= 1) {
            s0 += __shfl_xor_sync(0xffffffffu, s0, o);
            s1 += __shfl_xor_sync(0xffffffffu, s1, o);
        }
        if (lane == 0) { sv[i] = s0; tv[i] = s1; }
    }
    __syncthreads();

    // Process attention rows in groups of 5 (15 groups cover 75 rows).
    for (int g = 0; g < 15; g++) {
        const int i0 = g * 5;

        if (warp < 5) {
            const int i  = i0 + warp;
            const float si = sv[i];
            float ev[3];
            float m = -3.0e38f;
            #pragma unroll
            for (int r = 0; r < 3; r++) {
                const int j = lane + r * 32;
                float e;
                if (j < NNODE) {
                    e = si + tv[j];
                    e = (e > 0.0f) ? e : 0.2f * e;   // leaky relu
                    e += mb[i * NNODE + j];
                } else {
                    e = -3.0e38f;
                }
                ev[r] = e;
                m = fmaxf(m, e);
            }
            #pragma unroll
            for (int o = 16; o; o >>= 1)
                m = fmaxf(m, __shfl_xor_sync(0xffffffffu, m, o));
            float sum = 0.0f;
            #pragma unroll
            for (int r = 0; r < 3; r++) {
                const int j = lane + r * 32;
                const float p = (j < NNODE) ? __expf(ev[r] - m) : 0.0f;
                ev[r] = p;
                sum += p;
            }
            #pragma unroll
            for (int o = 16; o; o >>= 1)
                sum += __shfl_xor_sync(0xffffffffu, sum, o);
            const float inv = 1.0f / sum;
            #pragma unroll
            for (int r = 0; r < 3; r++) {
                const int j = lane + r * 32;
                if (j < NNODE) al[warp * 80 + j] = ev[r] * inv;
            }
        }
        __syncthreads();

        // out[i0..i0+4][col] = sum_j alpha[k][j] * h[j][col], col = tid
        const int col = tid;
        float a0 = 0.f, a1 = 0.f, a2 = 0.f, a3 = 0.f, a4 = 0.f;
        #pragma unroll 15
        for (int j = 0; j < NNODE; j++) {
            const float hv = hs[j * FOUT + col];
            a0 = fmaf(al[0 * 80 + j], hv, a0);
            a1 = fmaf(al[1 * 80 + j], hv, a1);
            a2 = fmaf(al[2 * 80 + j], hv, a2);
            a3 = fmaf(al[3 * 80 + j], hv, a3);
            a4 = fmaf(al[4 * 80 + j], hv, a4);
        }
        outb[(size_t)(i0 + 0) * 512 + col] = a0;
        outb[(size_t)(i0 + 1) * 512 + col] = a1;
        outb[(size_t)(i0 + 2) * 512 + col] = a2;
        outb[(size_t)(i0 + 3) * 512 + col] = a3;
        outb[(size_t)(i0 + 4) * 512 + col] = a4;
        __syncthreads();
    }
}

// ===========================================================================

extern "C" void kernel_launch(void* const* d_in, const int* in_sizes, int n_in,
                              void* d_out, int out_size)
{
    const float* X = (const float*)d_in[0];
    const int*   A = (const int*)d_in[1];
    const float* W = (const float*)d_in[2];
    const float* a = (const float*)d_in[3];
    float* out = (float*)d_out;

    cudaFuncSetAttribute(gat_attn_kernel,
                         cudaFuncAttributeMaxDynamicSharedMemorySize, SMEM_BYTES);

    dim3 g1(FOUT / BN, MROWS / BM);   // (2, 600)
    gat_gemm_kernel<<<g1, 256>>>(X, W, out);
    gat_attn_kernel<<<BATCH, 256, SMEM_BYTES>>>(A, a, out);
}

// round 4
// speedup vs baseline: 2.1042x; 2.1042x over previous
#include <cuda_runtime.h>
#include <cuda_bf16.h>
#include <cstdint>
#include <cstring>

// ---------------------------------------------------------------------------
// GAT layer: out = concat( softmax(mask(lrelu(s_i + t_j))) @ h , h )
//   X:[1024,75,512] fp32  A:[75,75] int32  W:[512,256] fp32  a:[2,256,1] fp32
//   out:[1024,75,512] fp32
// Phase 1: h = X @ W via bf16-split tensor-core GEMM -> out[..., 256:512]
// Phase 2: attention + aggregation -> out[..., 0:256]
// ---------------------------------------------------------------------------

#define BATCH 1024
#define NNODE 75
#define FIN   512
#define FOUT  256
#define MROWS (BATCH * NNODE)   // 76800

// ===================== Phase 1: bf16-split MMA GEMM ========================
// C = A@B, M=76800 K=512 N=256. CTA tile 128x128, BK=32, 256 thr (8 warps),
// warp tile 64x32 (2x4 warp grid). mma.sync.m16n8k16.bf16, fp32 accum.
// x = hi + lo (two bf16); C += Ahi*Bhi + Ahi*Blo + Alo*Bhi  (lo*lo dropped,
// ~2^-16 relative — far below the 1e-3 gate).

#define G_BM 128
#define G_BN 128
#define G_BK 32
#define SA 40     // A smem row stride (bf16 elems): 80B, conflict-free ldmatrix
#define SB 136    // B smem row stride: 272B, conflict-free ldmatrix
// stage layout in bf16 elems
#define A_HI_OFF 0
#define A_LO_OFF (G_BM * SA)                 // 5120
#define B_HI_OFF (2 * G_BM * SA)             // 10240
#define B_LO_OFF (2 * G_BM * SA + G_BK * SB) // 14592
#define STAGE_ELEMS (2 * G_BM * SA + 2 * G_BK * SB)  // 18944
#define GEMM_SMEM_BYTES (2 * STAGE_ELEMS * 2)        // 75776

__device__ __forceinline__ unsigned pack_bf16x2(float a, float b) {
    __nv_bfloat162 t = __floats2bfloat162_rn(a, b);
    unsigned u;
    memcpy(&u, &t, 4);
    return u;
}

__device__ __forceinline__ void ldsm_x4(unsigned r[4], unsigned addr) {
    asm volatile("ldmatrix.sync.aligned.m8n8.x4.shared.b16 {%0,%1,%2,%3}, [%4];"
                 : "=r"(r[0]), "=r"(r[1]), "=r"(r[2]), "=r"(r[3]) : "r"(addr));
}
__device__ __forceinline__ void ldsm_x2_t(unsigned r[2], unsigned addr) {
    asm volatile("ldmatrix.sync.aligned.m8n8.x2.trans.shared.b16 {%0,%1}, [%2];"
                 : "=r"(r[0]), "=r"(r[1]) : "r"(addr));
}
__device__ __forceinline__ void mma_bf16(float d[4], const unsigned a[4], const unsigned b[2]) {
    asm volatile(
        "mma.sync.aligned.m16n8k16.row.col.f32.bf16.bf16.f32 "
        "{%0,%1,%2,%3},{%4,%5,%6,%7},{%8,%9},{%0,%1,%2,%3};"
        : "+f"(d[0]), "+f"(d[1]), "+f"(d[2]), "+f"(d[3])
        : "r"(a[0]), "r"(a[1]), "r"(a[2]), "r"(a[3]), "r"(b[0]), "r"(b[1]));
}

__global__ __launch_bounds__(256, 1)
void gat_gemm_kernel(const float* __restrict__ X,
                     const float* __restrict__ W,
                     float* __restrict__ out)
{
    extern __shared__ __nv_bfloat16 sm[];
    const unsigned smem_u32 = (unsigned)__cvta_generic_to_shared(sm);

    const int tid  = threadIdx.x;
    const int lane = tid & 31;
    const int wid  = tid >> 5;
    const int warp_m = wid & 1;   // 2 warps along M (64 each)
    const int warp_n = wid >> 1;  // 4 warps along N (32 each)

    const float* Ap = X + (size_t)blockIdx.y * G_BM * FIN;
    const float* Bp = W + blockIdx.x * G_BN;

    float c[4][4][4];
    #pragma unroll
    for (int mt = 0; mt < 4; mt++)
        #pragma unroll
        for (int nt = 0; nt < 4; nt++)
            #pragma unroll
            for (int i = 0; i < 4; i++) c[mt][nt][i] = 0.0f;

    float4 aR[4], bR[4];

    // -------- loaders: per kstep, A 128x32 fp32 + B 32x128 fp32 -----------
    // A: idx = tid + l*256 -> row = idx>>3 (0..127), f4 = idx&7
    // B: idx = tid + l*256 -> row = idx>>5 (0..31),  f4 = idx&31
    auto load_regs = [&](int k0) {
        #pragma unroll
        for (int l = 0; l < 4; l++) {
            const int ia = tid + l * 256;
            aR[l] = *reinterpret_cast<const float4*>(
                Ap + (size_t)(ia >> 3) * FIN + k0 + (ia & 7) * 4);
            bR[l] = *reinterpret_cast<const float4*>(
                Bp + (size_t)(k0 + (ia >> 5)) * FOUT + (ia & 31) * 4);
        }
    };
    auto store_stage = [&](int s) {
        const int base = s * STAGE_ELEMS;
        #pragma unroll
        for (int l = 0; l < 4; l++) {
            const int ia = tid + l * 256;
            {
                const int off = (ia >> 3) * SA + (ia & 7) * 4;
                float4 v = aR[l];
                float h0 = __bfloat162float(__float2bfloat16(v.x));
                float h1 = __bfloat162float(__float2bfloat16(v.y));
                float h2 = __bfloat162float(__float2bfloat16(v.z));
                float h3 = __bfloat162float(__float2bfloat16(v.w));
                *reinterpret_cast<uint2*>(&sm[base + A_HI_OFF + off]) =
                    make_uint2(pack_bf16x2(v.x, v.y), pack_bf16x2(v.z, v.w));
                *reinterpret_cast<uint2*>(&sm[base + A_LO_OFF + off]) =
                    make_uint2(pack_bf16x2(v.x - h0, v.y - h1), pack_bf16x2(v.z - h2, v.w - h3));
            }
            {
                const int off = (ia >> 5) * SB + (ia & 31) * 4;
                float4 v = bR[l];
                float h0 = __bfloat162float(__float2bfloat16(v.x));
                float h1 = __bfloat162float(__float2bfloat16(v.y));
                float h2 = __bfloat162float(__float2bfloat16(v.z));
                float h3 = __bfloat162float(__float2bfloat16(v.w));
                *reinterpret_cast<uint2*>(&sm[base + B_HI_OFF + off]) =
                    make_uint2(pack_bf16x2(v.x, v.y), pack_bf16x2(v.z, v.w));
                *reinterpret_cast<uint2*>(&sm[base + B_LO_OFF + off]) =
                    make_uint2(pack_bf16x2(v.x - h0, v.y - h1), pack_bf16x2(v.z - h2, v.w - h3));
            }
        }
    };

    // prologue
    load_regs(0);
    store_stage(0);
    __syncthreads();

    #pragma unroll 1
    for (int t = 0; t < FIN / G_BK; t++) {
        if (t + 1 < FIN / G_BK) load_regs((t + 1) * G_BK);

        const int sbase = (t & 1) * STAGE_ELEMS;
        #pragma unroll
        for (int ks = 0; ks < 2; ks++) {
            // B fragments for this warp's 4 n8-tiles (hi and lo)
            unsigned bhi[4][2], blo[4][2];
            const int brow = ks * 16 + (lane & 15);
            #pragma unroll
            for (int nt = 0; nt < 4; nt++) {
                const int bcol = warp_n * 32 + nt * 8;
                ldsm_x2_t(bhi[nt], smem_u32 + 2u * (sbase + B_HI_OFF + brow * SB + bcol));
                ldsm_x2_t(blo[nt], smem_u32 + 2u * (sbase + B_LO_OFF + brow * SB + bcol));
            }
            const int arow = warp_m * 64 + (lane & 15);
            const int acol = ks * 16 + (lane >> 4) * 8;
            #pragma unroll
            for (int mt = 0; mt < 4; mt++) {
                unsigned ahi[4], alo[4];
                const int aoff = (arow + mt * 16) * SA + acol;
                ldsm_x4(ahi, smem_u32 + 2u * (sbase + A_HI_OFF + aoff));
                ldsm_x4(alo, smem_u32 + 2u * (sbase + A_LO_OFF + aoff));
                #pragma unroll
                for (int nt = 0; nt < 4; nt++) {
                    mma_bf16(c[mt][nt], ahi, bhi[nt]);
                    mma_bf16(c[mt][nt], ahi, blo[nt]);
                    mma_bf16(c[mt][nt], alo, bhi[nt]);
                }
            }
        }

        if (t + 1 < FIN / G_BK) {
            store_stage((t + 1) & 1);
            __syncthreads();
        }
    }

    // epilogue: write h into out[..., 256:512]
    const int row0 = blockIdx.y * G_BM + warp_m * 64 + (lane >> 2);
    const int col0 = blockIdx.x * G_BN + warp_n * 32 + (lane & 3) * 2;
    #pragma unroll
    for (int mt = 0; mt < 4; mt++) {
        #pragma unroll
        for (int nt = 0; nt < 4; nt++) {
            float* p0 = out + (size_t)(row0 + mt * 16) * 512 + 256 + col0 + nt * 8;
            float* p1 = out + (size_t)(row0 + mt * 16 + 8) * 512 + 256 + col0 + nt * 8;
            *reinterpret_cast<float2*>(p0) = make_float2(c[mt][nt][0], c[mt][nt][1]);
            *reinterpret_cast<float2*>(p1) = make_float2(c[mt][nt][2], c[mt][nt][3]);
        }
    }
}

// ===================== Phase 2: attention + aggregation ====================
// One block per batch, 256 threads. All 75 softmax rows computed once
// (in place over the mask-bias buffer), then a single aggregation pass:
// each thread owns 4 cols x 19 rows (76 fp32 accumulators).
#define MB_STRIDE 76
#define SM_HS   0
#define SM_MB   (SM_HS + NNODE * FOUT)            // 19200
#define SM_SV   (SM_MB + 76 * MB_STRIDE)          // 19200+5776 = 24976
#define SM_TV   (SM_SV + 80)                      // 25056
#define SM_TOTF (SM_TV + 80)                      // 25136
#define ATTN_SMEM_BYTES (SM_TOTF * 4)             // 100544

__global__ __launch_bounds__(256, 2)
void gat_attn_kernel(const int* __restrict__ A,
                     const float* __restrict__ avec,  // [2*256]
                     float* __restrict__ out)
{
    extern __shared__ float smf[];
    float* hs = smf + SM_HS;
    float* mb = smf + SM_MB;
    float* sv = smf + SM_SV;
    float* tv = smf + SM_TV;

    const int b    = blockIdx.x;
    const int tid  = threadIdx.x;
    const int warp = tid >> 5;
    const int lane = tid & 31;

    float* outb = out + (size_t)b * NNODE * 512;
    const float* hsrc = outb + 256;

    // Load h[b] (stride 512 -> packed 256), float4 granularity.
    for (int idx = tid; idx < NNODE * (FOUT / 4); idx += 256) {
        const int i  = idx >> 6;
        const int f4 = idx & 63;
        *reinterpret_cast<float4*>(&hs[i * FOUT + f4 * 4]) =
            *reinterpret_cast<const float4*>(hsrc + (size_t)i * 512 + f4 * 4);
    }
    // Mask bias with padded stride; zero the padding row 75.
    for (int idx = tid; idx < NNODE * NNODE; idx += 256)
        mb[(idx / NNODE) * MB_STRIDE + (idx % NNODE)] = A[idx] ? 0.0f : -1.0e9f;
    if (tid < MB_STRIDE) mb[75 * MB_STRIDE + tid] = 0.0f;
    __syncthreads();

    // s_i = h_i . a0 ; t_i = h_i . a1  (warp per row)
    for (int i = warp; i < NNODE; i += 8) {
        float s0 = 0.0f, s1 = 0.0f;
        #pragma unroll
        for (int r = 0; r < 8; r++) {
            const int f = lane + r * 32;
            const float hv = hs[i * FOUT + f];
            s0 = fmaf(hv, avec[f], s0);
            s1 = fmaf(hv, avec[256 + f], s1);
        }
        #pragma unroll
        for (int o = 16; o; o >>= 1) {
            s0 += __shfl_xor_sync(0xffffffffu, s0, o);
            s1 += __shfl_xor_sync(0xffffffffu, s1, o);
        }
        if (lane == 0) { sv[i] = s0; tv[i] = s1; }
    }
    __syncthreads();

    // Softmax of all 75 rows, written back in place over mb.
    for (int i = warp; i < NNODE; i += 8) {
        const float si = sv[i];
        float ev[3];
        float m = -3.0e38f;
        #pragma unroll
        for (int r = 0; r < 3; r++) {
            const int j = lane + r * 32;
            float e;
            if (j < NNODE) {
                e = si + tv[j];
                e = (e > 0.0f) ? e : 0.2f * e;     // leaky relu
                e += mb[i * MB_STRIDE + j];
            } else {
                e = -3.0e38f;
            }
            ev[r] = e;
            m = fmaxf(m, e);
        }
        #pragma unroll
        for (int o = 16; o; o >>= 1)
            m = fmaxf(m, __shfl_xor_sync(0xffffffffu, m, o));
        float sum = 0.0f;
        #pragma unroll
        for (int r = 0; r < 3; r++) {
            const int j = lane + r * 32;
            const float p = (j < NNODE) ? __expf(ev[r] - m) : 0.0f;
            ev[r] = p;
            sum += p;
        }
        #pragma unroll
        for (int o = 16; o; o >>= 1)
            sum += __shfl_xor_sync(0xffffffffu, sum, o);
        const float inv = 1.0f / sum;
        #pragma unroll
        for (int r = 0; r < 3; r++) {
            const int j = lane + r * 32;
            if (j < NNODE) mb[i * MB_STRIDE + j] = ev[r] * inv;
        }
    }
    __syncthreads();

    // Aggregation: thread owns cols [c4*4, c4*4+4) and rows {g, g+4, ..., g+72}.
    const int g  = tid >> 6;       // 0..3 (uniform per warp -> broadcast alpha loads)
    const int c4 = tid & 63;
    const float4* hs4 = reinterpret_cast<const float4*>(hs);

    float4 acc[19];
    #pragma unroll
    for (int r = 0; r < 19; r++) acc[r] = make_float4(0.f, 0.f, 0.f, 0.f);

    #pragma unroll 1
    for (int j = 0; j < NNODE; j++) {
        const float4 hv = hs4[j * 64 + c4];
        const float* ap = &mb[g * MB_STRIDE + j];
        #pragma unroll
        for (int r = 0; r < 19; r++) {
            const float a = ap[r * 4 * MB_STRIDE];   // row g+4r (row 75 pad = 0)
            acc[r].x = fmaf(a, hv.x, acc[r].x);
            acc[r].y = fmaf(a, hv.y, acc[r].y);
            acc[r].z = fmaf(a, hv.z, acc[r].z);
            acc[r].w = fmaf(a, hv.w, acc[r].w);
        }
    }
    #pragma unroll
    for (int r = 0; r < 19; r++) {
        const int row = g + 4 * r;
        if (row < NNODE)
            *reinterpret_cast<float4*>(outb + (size_t)row * 512 + c4 * 4) = acc[r];
    }
}

// ===========================================================================

extern "C" void kernel_launch(void* const* d_in, const int* in_sizes, int n_in,
                              void* d_out, int out_size)
{
    const float* X = (const float*)d_in[0];
    const int*   A = (const int*)d_in[1];
    const float* W = (const float*)d_in[2];
    const float* a = (const float*)d_in[3];
    float* out = (float*)d_out;

    cudaFuncSetAttribute(gat_gemm_kernel,
                         cudaFuncAttributeMaxDynamicSharedMemorySize, GEMM_SMEM_BYTES);
    cudaFuncSetAttribute(gat_attn_kernel,
                         cudaFuncAttributeMaxDynamicSharedMemorySize, ATTN_SMEM_BYTES);

    dim3 g1(FOUT / G_BN, MROWS / G_BM);   // (2, 600)
    gat_gemm_kernel<<<g1, 256, GEMM_SMEM_BYTES>>>(X, W, out);
    gat_attn_kernel<<<BATCH, 256, ATTN_SMEM_BYTES>>>(A, a, out);
}